// round 8
// baseline (speedup 1.0000x reference)
#include <cuda_runtime.h>

#define NSEG 128
#define EDIM 128
#define NHEAD 4
#define WARPS_PER_BLK 8
#define NBLK 1184   // 8 blocks/SM * 148 SMs

__device__ float g_s[NSEG * NHEAD];
__device__ float g_acc[NSEG * NHEAD * EDIM];
__device__ int   g_is64;
__device__ unsigned int g_done;

// Zero accumulators + completion counter + batch dtype detect (one launch).
__global__ void zero_kernel(const int* __restrict__ b32, int N) {
    int i = blockIdx.x * blockDim.x + threadIdx.x;
    if (i < NSEG * NHEAD * EDIM) g_acc[i] = 0.0f;
    if (i < NSEG * NHEAD)        g_s[i]   = 0.0f;
    if (i == 0) {
        g_done = 0;
        // int64 (LE): int32 view's high words at the tail are zero.
        int a = b32[N - 1];
        int b = (N >= 3) ? b32[N - 3] : 1;
        int c = (N >= 5) ? b32[N - 5] : 1;
        g_is64 = (a == 0 && b == 0 && c == 0) ? 1 : 0;
    }
}

__device__ __forceinline__ int load_seg(const void* batch, int n, int is64) {
    int v;
    if (is64) v = (int)((const long long*)batch)[n];
    else      v = ((const int*)batch)[n];
    return v & (NSEG - 1);
}

__device__ __forceinline__ float4 ldcs4(const float4* p) {
    return __ldcs(p);   // evict-first streaming load
}

__global__ __launch_bounds__(256) void att_kernel(
    const float4* __restrict__ x,        // [N, 32] float4 view of [N,128]
    const float4* __restrict__ w,        // [4, 32]
    const void*   __restrict__ batch,    // [N] sorted segment ids
    float* __restrict__ out,
    int N, int rpw)
{
    const int lane = threadIdx.x & 31;
    const int wid  = threadIdx.x >> 5;
    const int gw   = blockIdx.x * WARPS_PER_BLK + wid;
    int beg = gw * rpw;
    int end = beg + rpw; if (end > N) end = N;

    const int is64 = g_is64;

    if (beg < N) {
        float4 wv[NHEAD];
#pragma unroll
        for (int h = 0; h < NHEAD; ++h) wv[h] = w[h * 32 + lane];

        float  accS[NHEAD];
        float4 accA[NHEAD];
#pragma unroll
        for (int h = 0; h < NHEAD; ++h) {
            accS[h] = 0.0f;
            accA[h] = make_float4(0.0f, 0.0f, 0.0f, 0.0f);
        }

        int cur = load_seg(batch, beg, is64);

        // ---- depth-2 software pipeline ----
        int i1 = (beg + 1 < end) ? beg + 1 : end - 1;
        float4 xv0  = ldcs4(x + (size_t)beg * 32 + lane);
        float4 xv1  = ldcs4(x + (size_t)i1  * 32 + lane);
        int    sg0  = cur;
        int    sg1  = load_seg(batch, i1, is64);

        for (int n = beg; n < end; ++n) {
            float4 xv  = xv0;
            int    seg = sg0;
            xv0 = xv1; sg0 = sg1;
            if (n + 2 < end) {
                xv1 = ldcs4(x + (size_t)(n + 2) * 32 + lane);
                sg1 = load_seg(batch, n + 2, is64);
            }

            if (seg != cur) {
                if (lane == 0) {
#pragma unroll
                    for (int h = 0; h < NHEAD; ++h)
                        atomicAdd(&g_s[cur * NHEAD + h], accS[h]);
                }
#pragma unroll
                for (int h = 0; h < NHEAD; ++h) {
                    float* dst = &g_acc[(cur * NHEAD + h) * EDIM + lane * 4];
                    atomicAdd(dst + 0, accA[h].x);
                    atomicAdd(dst + 1, accA[h].y);
                    atomicAdd(dst + 2, accA[h].z);
                    atomicAdd(dst + 3, accA[h].w);
                    accA[h] = make_float4(0.0f, 0.0f, 0.0f, 0.0f);
                    accS[h] = 0.0f;
                }
                cur = seg;
            }

            float p[NHEAD];
#pragma unroll
            for (int h = 0; h < NHEAD; ++h)
                p[h] = xv.x * wv[h].x + xv.y * wv[h].y + xv.z * wv[h].z + xv.w * wv[h].w;

#pragma unroll
            for (int off = 16; off > 0; off >>= 1) {
#pragma unroll
                for (int h = 0; h < NHEAD; ++h)
                    p[h] += __shfl_xor_sync(0xffffffffu, p[h], off);
            }

#pragma unroll
            for (int h = 0; h < NHEAD; ++h) {
                float e = __expf(p[h]);
                accS[h]  += e;
                accA[h].x += e * xv.x;
                accA[h].y += e * xv.y;
                accA[h].z += e * xv.z;
                accA[h].w += e * xv.w;
            }
        }

        if (lane == 0) {
#pragma unroll
            for (int h = 0; h < NHEAD; ++h)
                atomicAdd(&g_s[cur * NHEAD + h], accS[h]);
        }
#pragma unroll
        for (int h = 0; h < NHEAD; ++h) {
            float* dst = &g_acc[(cur * NHEAD + h) * EDIM + lane * 4];
            atomicAdd(dst + 0, accA[h].x);
            atomicAdd(dst + 1, accA[h].y);
            atomicAdd(dst + 2, accA[h].z);
            atomicAdd(dst + 3, accA[h].w);
        }
    }

    // ---- inline finalize: last block reduces ----
    __shared__ int s_last;
    __threadfence();
    __syncthreads();
    if (threadIdx.x == 0) {
        unsigned int prev = atomicAdd(&g_done, 1u);
        s_last = (prev == (unsigned int)(gridDim.x - 1)) ? 1 : 0;
    }
    __syncthreads();
    if (s_last) {
        for (int i = threadIdx.x; i < NSEG * EDIM; i += 256) {
            int b = i >> 7;
            int e = i & 127;
            float r = 0.0f;
#pragma unroll
            for (int h = 0; h < NHEAD; ++h) {
                float av = __ldcg(&g_acc[(b * NHEAD + h) * EDIM + e]);
                float sv = __ldcg(&g_s[b * NHEAD + h]);
                r += av / sv;
            }
            out[i] = r * (1.0f / NHEAD);
        }
    }
}

extern "C" void kernel_launch(void* const* d_in, const int* in_sizes, int n_in,
                              void* d_out, int out_size) {
    const float* x     = (const float*)d_in[0];
    const float* w     = (const float*)d_in[1];
    const void*  batch = d_in[2];

    int N = in_sizes[0] / EDIM;
    int warps = NBLK * WARPS_PER_BLK;
    int rpw = (N + warps - 1) / warps;

    zero_kernel<<<(NSEG * NHEAD * EDIM + 255) / 256, 256>>>((const int*)batch, N);
    att_kernel<<<NBLK, 256>>>((const float4*)x, (const float4*)w, batch,
                              (float*)d_out, N, rpw);
}

// round 9
// speedup vs baseline: 1.9459x; 1.9459x over previous
#include <cuda_runtime.h>

#define NSEG 128
#define EDIM 128
#define NHEAD 4
#define WARPS_PER_BLK 8
#define NBLK 1184   // 8 blocks/SM * 148 SMs

__device__ float g_s[NSEG * NHEAD];
__device__ float g_acc[NSEG * NHEAD * EDIM];
__device__ int   g_is64;

// Zero accumulators + batch dtype detect (one launch).
__global__ void zero_kernel(const int* __restrict__ b32, int N) {
    int i = blockIdx.x * blockDim.x + threadIdx.x;
    if (i < NSEG * NHEAD * EDIM) g_acc[i] = 0.0f;
    if (i < NSEG * NHEAD)        g_s[i]   = 0.0f;
    if (i == 0) {
        // int64 (LE): int32 view's high words at the tail are zero.
        int a = b32[N - 1];
        int b = (N >= 3) ? b32[N - 3] : 1;
        int c = (N >= 5) ? b32[N - 5] : 1;
        g_is64 = (a == 0 && b == 0 && c == 0) ? 1 : 0;
    }
}

__device__ __forceinline__ int load_seg(const void* batch, int n, int is64) {
    int v;
    if (is64) v = (int)((const long long*)batch)[n];
    else      v = ((const int*)batch)[n];
    return v & (NSEG - 1);
}

__device__ __forceinline__ void flush_acc(
    int cur, int lane, float accS[NHEAD], float4 accA[NHEAD])
{
    if (lane == 0) {
#pragma unroll
        for (int h = 0; h < NHEAD; ++h)
            atomicAdd(&g_s[cur * NHEAD + h], accS[h]);
    }
#pragma unroll
    for (int h = 0; h < NHEAD; ++h) {
        float* dst = &g_acc[(cur * NHEAD + h) * EDIM + lane * 4];
        atomicAdd(dst + 0, accA[h].x);
        atomicAdd(dst + 1, accA[h].y);
        atomicAdd(dst + 2, accA[h].z);
        atomicAdd(dst + 3, accA[h].w);
    }
}

__device__ __forceinline__ void process_row(
    float4 xv, int seg, int& cur, int lane,
    float accS[NHEAD], float4 accA[NHEAD], const float4 wv[NHEAD])
{
    if (seg != cur) {
        flush_acc(cur, lane, accS, accA);
#pragma unroll
        for (int h = 0; h < NHEAD; ++h) {
            accS[h] = 0.0f;
            accA[h] = make_float4(0.0f, 0.0f, 0.0f, 0.0f);
        }
        cur = seg;
    }

    float p[NHEAD];
#pragma unroll
    for (int h = 0; h < NHEAD; ++h)
        p[h] = xv.x * wv[h].x + xv.y * wv[h].y + xv.z * wv[h].z + xv.w * wv[h].w;

#pragma unroll
    for (int off = 16; off > 0; off >>= 1) {
#pragma unroll
        for (int h = 0; h < NHEAD; ++h)
            p[h] += __shfl_xor_sync(0xffffffffu, p[h], off);
    }

#pragma unroll
    for (int h = 0; h < NHEAD; ++h) {
        float e = __expf(p[h]);
        accS[h]  += e;
        accA[h].x += e * xv.x;
        accA[h].y += e * xv.y;
        accA[h].z += e * xv.z;
        accA[h].w += e * xv.w;
    }
}

__global__ __launch_bounds__(256, 4) void att_kernel(
    const float4* __restrict__ x,        // [N, 32] float4 view of [N,128]
    const float4* __restrict__ w,        // [4, 32]
    const void*   __restrict__ batch,    // [N] sorted segment ids
    int N, int rpw)
{
    const int lane = threadIdx.x & 31;
    const int wid  = threadIdx.x >> 5;
    const int gw   = blockIdx.x * WARPS_PER_BLK + wid;
    int beg = gw * rpw;
    if (beg >= N) return;
    int end = beg + rpw; if (end > N) end = N;

    const int is64 = g_is64;

    float4 wv[NHEAD];
#pragma unroll
    for (int h = 0; h < NHEAD; ++h) wv[h] = w[h * 32 + lane];

    float  accS[NHEAD];
    float4 accA[NHEAD];
#pragma unroll
    for (int h = 0; h < NHEAD; ++h) {
        accS[h] = 0.0f;
        accA[h] = make_float4(0.0f, 0.0f, 0.0f, 0.0f);
    }

    int cur = load_seg(batch, beg, is64);

    // ---- depth-2 pipeline, branch-free rotation ----
    int i1 = (beg + 1 < end) ? beg + 1 : end - 1;
    float4 xv0 = x[(size_t)beg * 32 + lane];
    float4 xv1 = x[(size_t)i1  * 32 + lane];
    int    sg0 = cur;
    int    sg1 = load_seg(batch, i1, is64);

    int n = beg;
    for (; n + 2 < end; ++n) {
        float4 xv  = xv0;
        int    seg = sg0;
        xv0 = xv1; sg0 = sg1;
        xv1 = x[(size_t)(n + 2) * 32 + lane];
        sg1 = load_seg(batch, n + 2, is64);
        process_row(xv, seg, cur, lane, accS, accA, wv);
    }
    // epilogue: rows n (=xv0) and, if present, n+1 (=xv1)
    process_row(xv0, sg0, cur, lane, accS, accA, wv);
    if (n + 1 < end)
        process_row(xv1, sg1, cur, lane, accS, accA, wv);

    flush_acc(cur, lane, accS, accA);
}

__global__ void finalize_kernel(float* __restrict__ out) {
    int b = blockIdx.x;
    int e = threadIdx.x;
    float r = 0.0f;
#pragma unroll
    for (int h = 0; h < NHEAD; ++h)
        r += g_acc[(b * NHEAD + h) * EDIM + e] / g_s[b * NHEAD + h];
    out[b * EDIM + e] = r * (1.0f / NHEAD);
}

extern "C" void kernel_launch(void* const* d_in, const int* in_sizes, int n_in,
                              void* d_out, int out_size) {
    const float* x     = (const float*)d_in[0];
    const float* w     = (const float*)d_in[1];
    const void*  batch = d_in[2];

    int N = in_sizes[0] / EDIM;
    int warps = NBLK * WARPS_PER_BLK;
    int rpw = (N + warps - 1) / warps;

    zero_kernel<<<(NSEG * NHEAD * EDIM + 255) / 256, 256>>>((const int*)batch, N);
    att_kernel<<<NBLK, 256>>>((const float4*)x, (const float4*)w, batch, N, rpw);
    finalize_kernel<<<NSEG, EDIM>>>((float*)d_out);
}